// round 5
// baseline (speedup 1.0000x reference)
#include <cuda_runtime.h>
#include <math.h>
#include <stdint.h>

// ---------------------------------------------------------------------------
// ENAS controller sampler. H=2048, NB=8, NC=8, TEMP=5, TANH_C=2.5, OP_RED=2.5
// Sequence: 2 samplers x (2 warmup LSTM + 8 layers x (2 idx steps + 2 op steps
// + 1 anchor step)). All control flow data-dependence resolved on device via
// g_sel[]; host emits a fixed sequence of ~220 kernel launches (graph-safe).
// ---------------------------------------------------------------------------

#define H 2048
#define G4 8192   // 4*H

// scratch layout (floats)
#define OFF_H0   0
#define OFF_H1   (OFF_H0 + H)
#define OFF_C    (OFF_H1 + H)
#define OFF_HW2  (OFF_C + H)
#define OFF_AW1  (OFF_HW2 + H)            // 10 x 2048
#define OFF_AXP  (OFF_AW1 + 10*H)         // 10 x 8192 anchor x-projections
#define OFF_EXP  (OFF_AXP + 10*G4)        // 9 x 8192 encoder x-projections
#define SCR_TOTAL (OFF_EXP + 9*G4)

__device__ __align__(16) float    g_scratch[SCR_TOTAL];
__device__ int       g_sel[64];
__device__ unsigned  g_key[2];
__device__ float     g_acc[2];   // [0]=log_prob, [1]=entropy

// ------------------------- Threefry-2x32 (20 rounds) -----------------------
__device__ __forceinline__ void tf2x32(unsigned k0, unsigned k1,
                                       unsigned x0, unsigned x1,
                                       unsigned &y0, unsigned &y1)
{
    const unsigned ks0 = k0, ks1 = k1, ks2 = k0 ^ k1 ^ 0x1BD11BDAu;
    x0 += ks0; x1 += ks1;
    const unsigned R[8] = {13u,15u,26u,6u,17u,29u,16u,24u};
    unsigned ks[3] = {ks0, ks1, ks2};
    #pragma unroll
    for (int i = 0; i < 5; i++) {
        #pragma unroll
        for (int j = 0; j < 4; j++) {
            unsigned r = R[(i & 1) * 4 + j];
            x0 += x1;
            x1 = (x1 << r) | (x1 >> (32u - r));
            x1 ^= x0;
        }
        x0 += ks[(i + 1) % 3];
        x1 += ks[(i + 2) % 3] + (unsigned)(i + 1);
    }
    y0 = x0; y1 = x1;
}

// partitionable-mode sampling: split + gumbel-argmax + log_softmax accounting
__device__ void do_sample(const float* l, int n, unsigned* key, float* acc,
                          int* sel_slot, float* arc_out)
{
    unsigned k0 = key[0], k1 = key[1];
    unsigned nk0, nk1, s0, s1;
    tf2x32(k0, k1, 0u, 0u, nk0, nk1);   // new carry key
    tf2x32(k0, k1, 0u, 1u, s0, s1);     // subkey for this draw
    key[0] = nk0; key[1] = nk1;

    int best = 0; float bz = -3.4e38f;
    for (int a = 0; a < n; a++) {
        unsigned b1, b2;
        tf2x32(s0, s1, 0u, (unsigned)a, b1, b2);
        unsigned bits = b1 ^ b2;
        float f = __uint_as_float((bits >> 9) | 0x3F800000u) - 1.0f;
        float u = (f == 0.0f) ? 1.17549435e-38f : f;
        float g = -logf(-logf(u));
        float z = l[a] + g;
        if (z > bz) { bz = z; best = a; }
    }
    float mx = l[0];
    for (int a = 1; a < n; a++) mx = fmaxf(mx, l[a]);
    float se = 0.0f;
    for (int a = 0; a < n; a++) se += expf(l[a] - mx);
    float lse = logf(se);
    acc[0] += -((l[best] - mx) - lse);
    float ent = 0.0f;
    for (int a = 0; a < n; a++) {
        float ls = (l[a] - mx) - lse;
        ent -= ls * expf(ls);
    }
    acc[1] += ent;
    *sel_slot = best;
    *arc_out = (float)best;
}

// ------------------------------ kernels ------------------------------------
__global__ void init_kernel(float* h0, float* c, float* axp01,
                            unsigned* key, float* acc)
{
    int i = blockIdx.x * blockDim.x + threadIdx.x;
    if (i < H)        { h0[i] = 0.0f; c[i] = 0.0f; }
    if (i < 2 * G4)   axp01[i] = 0.0f;
    if (i == 0) { key[0] = 0u; key[1] = 42u; acc[0] = 0.0f; acc[1] = 0.0f; }
}

// encoder_xproj[e][j] = sum_k encoder_w[e,k] * w_ih[j,k]   (reads w_ih once)
__global__ void encproj_kernel(const float* __restrict__ w_ih,
                               const float* __restrict__ enc,
                               float* __restrict__ expo)
{
    int j = blockIdx.x;          // 0..8191
    int t = threadIdx.x;         // 128 threads
    const float4* w4 = (const float4*)(w_ih + (size_t)j * H);
    const float4* e4 = (const float4*)enc;
    float acc[9];
    #pragma unroll
    for (int e = 0; e < 9; e++) acc[e] = 0.0f;
    #pragma unroll
    for (int i = 0; i < 4; i++) {
        int idx = t + i * 128;
        float4 w = w4[idx];
        #pragma unroll
        for (int e = 0; e < 9; e++) {
            float4 v = e4[e * 512 + idx];
            acc[e] += w.x * v.x + w.y * v.y + w.z * v.z + w.w * v.w;
        }
    }
    __shared__ float sred[9][4];
    #pragma unroll
    for (int e = 0; e < 9; e++) {
        float s = acc[e];
        for (int o = 16; o > 0; o >>= 1) s += __shfl_down_sync(0xffffffffu, s, o);
        if ((t & 31) == 0) sred[e][t >> 5] = s;
    }
    __syncthreads();
    if (t < 9) {
        float s = sred[t][0] + sred[t][1] + sred[t][2] + sred[t][3];
        expo[(size_t)t * G4 + j] = s;
    }
}

// generic matvec: out[r] = sum_k W[r*2048+k] * x[k], gridDim.x = R
__global__ void matvec_kernel(const float* __restrict__ W,
                              const float* __restrict__ x,
                              float* __restrict__ out)
{
    int r = blockIdx.x, t = threadIdx.x;  // 128 threads
    const float4* w4 = (const float4*)(W + (size_t)r * H);
    const float4* x4 = (const float4*)x;
    float s = 0.0f;
    #pragma unroll
    for (int i = 0; i < 4; i++) {
        int idx = t + i * 128;
        float4 w = w4[idx];
        float4 v = x4[idx];
        s += w.x * v.x + w.y * v.y + w.z * v.z + w.w * v.w;
    }
    __shared__ float sred[4];
    for (int o = 16; o > 0; o >>= 1) s += __shfl_down_sync(0xffffffffu, s, o);
    if ((t & 31) == 0) sred[t >> 5] = s;
    __syncthreads();
    if (t == 0) out[r] = sred[0] + sred[1] + sred[2] + sred[3];
}

// One LSTM cell step. xproj precomputed; sel (optional) picks the slot.
__global__ void lstm_kernel(const float* __restrict__ w_hh,
                            const float* __restrict__ b_ih,
                            const float* __restrict__ b_hh,
                            const float* __restrict__ xproj_base,
                            const int* __restrict__ sel, int sel_off,
                            const float* __restrict__ h_in,
                            float* __restrict__ h_out,
                            float* __restrict__ c)
{
    __shared__ float sh[H];
    __shared__ float sred[4][4];
    int j = blockIdx.x;      // 0..2047
    int t = threadIdx.x;     // 128 threads
    const float* xp = xproj_base;
    if (sel) xp += (size_t)(*sel + sel_off) * G4;

    const float4* h4 = (const float4*)h_in;
    float4* sh4 = (float4*)sh;
    for (int i = t; i < 512; i += 128) sh4[i] = h4[i];
    __syncthreads();

    float acc[4];
    #pragma unroll
    for (int g = 0; g < 4; g++) {
        const float4* w4 = (const float4*)(w_hh + ((size_t)(g * H + j)) * H);
        float s = 0.0f;
        #pragma unroll
        for (int i = 0; i < 4; i++) {
            int idx = t + i * 128;
            float4 w = w4[idx];
            float4 h = sh4[idx];
            s += w.x * h.x + w.y * h.y + w.z * h.z + w.w * h.w;
        }
        acc[g] = s;
    }
    #pragma unroll
    for (int g = 0; g < 4; g++) {
        float s = acc[g];
        for (int o = 16; o > 0; o >>= 1) s += __shfl_down_sync(0xffffffffu, s, o);
        if ((t & 31) == 0) sred[g][t >> 5] = s;
    }
    __syncthreads();
    if (t == 0) {
        float gi = sred[0][0]+sred[0][1]+sred[0][2]+sred[0][3] + xp[j]       + b_ih[j]       + b_hh[j];
        float gf = sred[1][0]+sred[1][1]+sred[1][2]+sred[1][3] + xp[j+H]     + b_ih[j+H]     + b_hh[j+H];
        float gg = sred[2][0]+sred[2][1]+sred[2][2]+sred[2][3] + xp[j+2*H]   + b_ih[j+2*H]   + b_hh[j+2*H];
        float go = sred[3][0]+sred[3][1]+sred[3][2]+sred[3][3] + xp[j+3*H]   + b_ih[j+3*H]   + b_hh[j+3*H];
        float si = 1.0f / (1.0f + expf(-gi));
        float sf = 1.0f / (1.0f + expf(-gf));
        float so = 1.0f / (1.0f + expf(-go));
        float cn = sf * c[j] + si * tanhf(gg);
        c[j] = cn;
        h_out[j] = so * tanhf(cn);
    }
}

// attention logits over n anchors + sample (single block, 256 threads)
__global__ void idx_sample_kernel(const float* __restrict__ v_attn,
                                  const float* __restrict__ aw1,
                                  const float* __restrict__ hw2,
                                  int n, int* sel_slot, float* arc_out,
                                  unsigned* key, float* acc)
{
    __shared__ float slog[10];
    __shared__ float sred[8];
    int t = threadIdx.x;
    for (int a = 0; a < n; a++) {
        float s = 0.0f;
        for (int k = t; k < H; k += 256)
            s += tanhf(aw1[(size_t)a * H + k] + hw2[k]) * v_attn[k];
        for (int o = 16; o > 0; o >>= 1) s += __shfl_down_sync(0xffffffffu, s, o);
        if ((t & 31) == 0) sred[t >> 5] = s;
        __syncthreads();
        if (t == 0) {
            float tot = 0.0f;
            for (int w = 0; w < 8; w++) tot += sred[w];
            slog[a] = tot;
        }
        __syncthreads();
    }
    if (t == 0) {
        float l[10];
        for (int a = 0; a < n; a++) l[a] = 2.5f * tanhf(slog[a] / 5.0f);
        do_sample(l, n, key, acc, sel_slot, arc_out);
    }
}

// op logits + sample (single block, 256 threads)
__global__ void op_sample_kernel(const float* __restrict__ h,
                                 const float* __restrict__ w_soft,
                                 const float* __restrict__ b_soft,
                                 const float* __restrict__ b_nl,
                                 int use_bias,
                                 int* sel_slot, float* arc_out,
                                 unsigned* key, float* acc)
{
    __shared__ float slog[8];
    __shared__ float sred[8];
    int t = threadIdx.x;
    for (int r = 0; r < 8; r++) {
        float s = 0.0f;
        for (int k = t; k < H; k += 256) s += h[k] * w_soft[(size_t)r * H + k];
        for (int o = 16; o > 0; o >>= 1) s += __shfl_down_sync(0xffffffffu, s, o);
        if ((t & 31) == 0) sred[t >> 5] = s;
        __syncthreads();
        if (t == 0) {
            float tot = 0.0f;
            for (int w = 0; w < 8; w++) tot += sred[w];
            slog[r] = tot;
        }
        __syncthreads();
    }
    if (t == 0) {
        float l[8];
        for (int r = 0; r < 8; r++) {
            float v = tanhf((slog[r] + b_soft[r]) / 5.0f);  // *(TANH_C/OP_RED)=1
            if (use_bias) v += b_nl[r];
            l[r] = v;
        }
        do_sample(l, 8, key, acc, sel_slot, arc_out);
    }
}

__global__ void final_kernel(const float* acc, float* out)
{
    out[64] = acc[0];
    out[65] = acc[1];
}

// ------------------------------- launcher ----------------------------------
extern "C" void kernel_launch(void* const* d_in, const int* in_sizes, int n_in,
                              void* d_out, int out_size)
{
    const float* enc    = (const float*)d_in[0];
    const float* w_ih   = (const float*)d_in[1];
    const float* b_ih   = (const float*)d_in[2];
    const float* w_hh   = (const float*)d_in[3];
    const float* b_hh   = (const float*)d_in[4];
    const float* w_soft = (const float*)d_in[5];
    const float* b_soft = (const float*)d_in[6];
    const float* b_nl   = (const float*)d_in[7];
    const float* w_a1   = (const float*)d_in[8];
    const float* w_a2   = (const float*)d_in[9];
    const float* v_at   = (const float*)d_in[10];
    float* out = (float*)d_out;

    float* scr = nullptr; unsigned* key = nullptr; float* acc = nullptr; int* sel = nullptr;
    cudaGetSymbolAddress((void**)&scr, g_scratch);
    cudaGetSymbolAddress((void**)&key, g_key);
    cudaGetSymbolAddress((void**)&acc, g_acc);
    cudaGetSymbolAddress((void**)&sel, g_sel);

    float* hbuf[2] = { scr + OFF_H0, scr + OFF_H1 };
    float* c    = scr + OFF_C;
    float* hw2  = scr + OFF_HW2;
    float* aw1  = scr + OFF_AW1;
    float* axp  = scr + OFF_AXP;
    float* expo = scr + OFF_EXP;

    init_kernel<<<64, 256>>>(hbuf[0], c, axp, key, acc);
    encproj_kernel<<<G4, 128>>>(w_ih, enc, expo);

    int hp = 0;   // current h buffer
    int tc = 0;   // temporal decision counter (0..63)
    for (int s = 0; s < 2; s++) {
        int ub = (s == 0) ? 1 : 0;
        // warmup: 2 LSTM steps on encoder row 0; aw1[0..1] = h @ w_attn_1.T
        for (int w = 0; w < 2; w++) {
            lstm_kernel<<<H, 128>>>(w_hh, b_ih, b_hh, expo, nullptr, 0,
                                    hbuf[hp], hbuf[hp ^ 1], c); hp ^= 1;
            matvec_kernel<<<H, 128>>>(w_a1, hbuf[hp], aw1 + (size_t)w * H);
        }
        for (int l = 0; l < 8; l++) {
            int n = l + 2;
            int base = s * 32 + l * 4;
            // idx decision 0 (input = encoder row 0)
            lstm_kernel<<<H, 128>>>(w_hh, b_ih, b_hh, expo, nullptr, 0,
                                    hbuf[hp], hbuf[hp ^ 1], c); hp ^= 1;
            matvec_kernel<<<H, 128>>>(w_a2, hbuf[hp], hw2);
            idx_sample_kernel<<<1, 256>>>(v_at, aw1, hw2, n, sel + tc,
                                          out + base + 0, key, acc);
            int t0 = tc++;
            // idx decision 1 (input = anchors[idx0] -> precomputed xproj slot)
            lstm_kernel<<<H, 128>>>(w_hh, b_ih, b_hh, axp, sel + t0, 0,
                                    hbuf[hp], hbuf[hp ^ 1], c); hp ^= 1;
            matvec_kernel<<<H, 128>>>(w_a2, hbuf[hp], hw2);
            idx_sample_kernel<<<1, 256>>>(v_at, aw1, hw2, n, sel + tc,
                                          out + base + 2, key, acc);
            int t1 = tc++;
            // op decision 0 (input = anchors[idx1])
            lstm_kernel<<<H, 128>>>(w_hh, b_ih, b_hh, axp, sel + t1, 0,
                                    hbuf[hp], hbuf[hp ^ 1], c); hp ^= 1;
            op_sample_kernel<<<1, 256>>>(hbuf[hp], w_soft, b_soft, b_nl, ub,
                                         sel + tc, out + base + 1, key, acc);
            int t2 = tc++;
            // op decision 1 (input = encoder[op0 + 1])
            lstm_kernel<<<H, 128>>>(w_hh, b_ih, b_hh, expo, sel + t2, 1,
                                    hbuf[hp], hbuf[hp ^ 1], c); hp ^= 1;
            op_sample_kernel<<<1, 256>>>(hbuf[hp], w_soft, b_soft, b_nl, ub,
                                         sel + tc, out + base + 3, key, acc);
            int t3 = tc++;
            // anchor step (input = encoder[op1 + 1]); store aw1/axp for slot n
            lstm_kernel<<<H, 128>>>(w_hh, b_ih, b_hh, expo, sel + t3, 1,
                                    hbuf[hp], hbuf[hp ^ 1], c); hp ^= 1;
            matvec_kernel<<<H, 128>>>(w_a1, hbuf[hp], aw1 + (size_t)n * H);
            matvec_kernel<<<G4, 128>>>(w_ih, hbuf[hp], axp + (size_t)n * G4);
        }
    }
    final_kernel<<<1, 1>>>(acc, out);
}

// round 6
// speedup vs baseline: 1.1769x; 1.1769x over previous
#include <cuda_runtime.h>
#include <math.h>
#include <stdint.h>

// ---------------------------------------------------------------------------
// ENAS controller sampler. H=2048, NB=8, NC=8, TEMP=5, TANH_C=2.5, OP_RED=2.5
// R5: MLP=8 front-batched loads, 256-thr/4-row blocks, last-block fusion of
// samplers (threadfence+ticket), __ldcs streaming for w_ih to keep w_hh
// L2-resident. ~140 launches total.
// ---------------------------------------------------------------------------

#define H 2048
#define G4 8192   // 4*H

// scratch layout (floats)
#define OFF_H0   0
#define OFF_H1   (OFF_H0 + H)
#define OFF_C    (OFF_H1 + H)
#define OFF_HW2  (OFF_C + H)
#define OFF_AW1  (OFF_HW2 + H)            // 10 x 2048
#define OFF_AXP  (OFF_AW1 + 10*H)         // 10 x 8192 anchor x-projections
#define OFF_EXP  (OFF_AXP + 10*G4)        // 9 x 8192 encoder x-projections
#define SCR_TOTAL (OFF_EXP + 9*G4)

__device__ __align__(16) float    g_scratch[SCR_TOTAL];
__device__ int       g_sel[64];
__device__ unsigned  g_key[2];
__device__ float     g_acc[2];   // [0]=log_prob, [1]=entropy
__device__ unsigned  g_ctr[4];   // arrival counters for last-block fusion

// ------------------------- Threefry-2x32 (20 rounds) -----------------------
__device__ __forceinline__ void tf2x32(unsigned k0, unsigned k1,
                                       unsigned x0, unsigned x1,
                                       unsigned &y0, unsigned &y1)
{
    const unsigned ks0 = k0, ks1 = k1, ks2 = k0 ^ k1 ^ 0x1BD11BDAu;
    x0 += ks0; x1 += ks1;
    const unsigned R[8] = {13u,15u,26u,6u,17u,29u,16u,24u};
    unsigned ks[3] = {ks0, ks1, ks2};
    #pragma unroll
    for (int i = 0; i < 5; i++) {
        #pragma unroll
        for (int j = 0; j < 4; j++) {
            unsigned r = R[(i & 1) * 4 + j];
            x0 += x1;
            x1 = (x1 << r) | (x1 >> (32u - r));
            x1 ^= x0;
        }
        x0 += ks[(i + 1) % 3];
        x1 += ks[(i + 2) % 3] + (unsigned)(i + 1);
    }
    y0 = x0; y1 = x1;
}

// partitionable-mode sampling: split + gumbel-argmax + log_softmax accounting
__device__ void do_sample(const float* l, int n, unsigned* key, float* acc,
                          int* sel_slot, float* arc_out)
{
    unsigned k0 = key[0], k1 = key[1];
    unsigned nk0, nk1, s0, s1;
    tf2x32(k0, k1, 0u, 0u, nk0, nk1);   // new carry key
    tf2x32(k0, k1, 0u, 1u, s0, s1);     // subkey for this draw
    key[0] = nk0; key[1] = nk1;

    int best = 0; float bz = -3.4e38f;
    for (int a = 0; a < n; a++) {
        unsigned b1, b2;
        tf2x32(s0, s1, 0u, (unsigned)a, b1, b2);
        unsigned bits = b1 ^ b2;
        float f = __uint_as_float((bits >> 9) | 0x3F800000u) - 1.0f;
        float u = (f == 0.0f) ? 1.17549435e-38f : f;
        float g = -logf(-logf(u));
        float z = l[a] + g;
        if (z > bz) { bz = z; best = a; }
    }
    float mx = l[0];
    for (int a = 1; a < n; a++) mx = fmaxf(mx, l[a]);
    float se = 0.0f;
    for (int a = 0; a < n; a++) se += expf(l[a] - mx);
    float lse = logf(se);
    acc[0] += -((l[best] - mx) - lse);
    float ent = 0.0f;
    for (int a = 0; a < n; a++) {
        float ls = (l[a] - mx) - lse;
        ent -= ls * expf(ls);
    }
    acc[1] += ent;
    *sel_slot = best;
    *arc_out = (float)best;
}

// ------------------------------ kernels ------------------------------------
__global__ void init_kernel(float* h0, float* c, float* axp01,
                            unsigned* key, float* acc, unsigned* ctr)
{
    int i = blockIdx.x * blockDim.x + threadIdx.x;
    if (i < H)        { h0[i] = 0.0f; c[i] = 0.0f; }
    if (i < 2 * G4)   axp01[i] = 0.0f;
    if (i == 0) {
        key[0] = 0u; key[1] = 42u; acc[0] = 0.0f; acc[1] = 0.0f;
        ctr[0] = 0u; ctr[1] = 0u; ctr[2] = 0u; ctr[3] = 0u;
    }
}

// encoder_xproj[e][j] = sum_k encoder_w[e,k] * w_ih[j,k]  (streams w_ih once)
__global__ void encproj_kernel(const float* __restrict__ w_ih,
                               const float* __restrict__ enc,
                               float* __restrict__ expo)
{
    int j = blockIdx.x;          // 0..8191
    int t = threadIdx.x;         // 128 threads
    const float4* w4 = (const float4*)(w_ih + (size_t)j * H);
    const float4* e4 = (const float4*)enc;
    float4 w[4];
    #pragma unroll
    for (int i = 0; i < 4; i++) w[i] = __ldcs(&w4[t + i * 128]);
    float acc[9];
    #pragma unroll
    for (int e = 0; e < 9; e++) acc[e] = 0.0f;
    #pragma unroll
    for (int i = 0; i < 4; i++) {
        int idx = t + i * 128;
        #pragma unroll
        for (int e = 0; e < 9; e++) {
            float4 v = e4[e * 512 + idx];
            acc[e] += w[i].x * v.x + w[i].y * v.y + w[i].z * v.z + w[i].w * v.w;
        }
    }
    __shared__ float sred[9][4];
    #pragma unroll
    for (int e = 0; e < 9; e++) {
        float s = acc[e];
        for (int o = 16; o > 0; o >>= 1) s += __shfl_down_sync(0xffffffffu, s, o);
        if ((t & 31) == 0) sred[e][t >> 5] = s;
    }
    __syncthreads();
    if (t < 9) {
        float s = sred[t][0] + sred[t][1] + sred[t][2] + sred[t][3];
        expo[(size_t)t * G4 + j] = s;
    }
}

// One LSTM cell step; 4 gate-rows of column j per block, 256 threads,
// 8 front-batched LDG.128 per thread. Optional fused op-sample (last block).
__global__ void __launch_bounds__(256)
lstm_kernel(const float* __restrict__ w_hh,
            const float* __restrict__ b_ih,
            const float* __restrict__ b_hh,
            const float* __restrict__ xproj_base,
            const int* __restrict__ sel, int sel_off,
            const float* __restrict__ h_in,
            float* __restrict__ h_out,
            float* __restrict__ c,
            // fused op-sample (w_soft==nullptr disables)
            const float* __restrict__ w_soft,
            const float* __restrict__ b_soft,
            const float* __restrict__ b_nl, int use_bias,
            int* sel_slot, float* arc_out,
            unsigned* key, float* acc, unsigned* ctr)
{
    __shared__ float4 sh4[512];
    __shared__ float sred[8];
    __shared__ unsigned s_ticket;
    int j = blockIdx.x;      // 0..2047
    int t = threadIdx.x;     // 256 threads
    int g = t >> 6;          // gate 0..3
    int r = t & 63;          // lane within row

    const float4* w4 = (const float4*)(w_hh + ((size_t)(g * H + j)) * H);
    float4 w[8];
    #pragma unroll
    for (int i = 0; i < 8; i++) w[i] = w4[r + i * 64];

    const float4* h4 = (const float4*)h_in;
    sh4[t]       = h4[t];
    sh4[t + 256] = h4[t + 256];
    __syncthreads();

    float s = 0.0f;
    #pragma unroll
    for (int i = 0; i < 8; i++) {
        float4 h = sh4[r + i * 64];
        s += w[i].x * h.x + w[i].y * h.y + w[i].z * h.z + w[i].w * h.w;
    }
    for (int o = 16; o > 0; o >>= 1) s += __shfl_down_sync(0xffffffffu, s, o);
    if ((t & 31) == 0) sred[t >> 5] = s;
    __syncthreads();
    if (t == 0) {
        const float* xp = xproj_base;
        if (sel) xp += (size_t)(*sel + sel_off) * G4;
        float gi = sred[0] + sred[1] + xp[j]       + b_ih[j]       + b_hh[j];
        float gf = sred[2] + sred[3] + xp[j +   H] + b_ih[j +   H] + b_hh[j +   H];
        float gg = sred[4] + sred[5] + xp[j + 2*H] + b_ih[j + 2*H] + b_hh[j + 2*H];
        float go = sred[6] + sred[7] + xp[j + 3*H] + b_ih[j + 3*H] + b_hh[j + 3*H];
        float si = 1.0f / (1.0f + expf(-gi));
        float sf = 1.0f / (1.0f + expf(-gf));
        float so = 1.0f / (1.0f + expf(-go));
        float cn = sf * c[j] + si * tanhf(gg);
        c[j] = cn;
        h_out[j] = so * tanhf(cn);
    }

    if (w_soft) {
        if (t == 0) {
            __threadfence();
            s_ticket = atomicAdd(ctr, 1u);
        }
        __syncthreads();
        if (s_ticket == gridDim.x - 1) {
            __threadfence();
            __shared__ float slog[8];
            for (int rr = 0; rr < 8; rr++) {
                float ss = 0.0f;
                for (int k = t; k < H; k += 256)
                    ss += h_out[k] * w_soft[(size_t)rr * H + k];
                for (int o = 16; o > 0; o >>= 1)
                    ss += __shfl_down_sync(0xffffffffu, ss, o);
                if ((t & 31) == 0) sred[t >> 5] = ss;
                __syncthreads();
                if (t == 0) {
                    float tot = 0.0f;
                    for (int wp = 0; wp < 8; wp++) tot += sred[wp];
                    slog[rr] = tot;
                }
                __syncthreads();
            }
            if (t == 0) {
                float l[8];
                for (int rr = 0; rr < 8; rr++) {
                    float v = tanhf((slog[rr] + b_soft[rr]) / 5.0f); // *(2.5/2.5)=1
                    if (use_bias) v += b_nl[rr];
                    l[rr] = v;
                }
                do_sample(l, 8, key, acc, sel_slot, arc_out);
                *ctr = 0;
            }
        }
    }
}

// Fused: hw2 = w_a2 @ h (4 rows/block), then last block computes attention
// logits over n anchors and samples. grid = H/4 = 512 blocks, 256 threads.
__global__ void __launch_bounds__(256)
attn_kernel(const float* __restrict__ w_a2,
            const float* __restrict__ h_in,
            float* __restrict__ hw2,
            const float* __restrict__ v_attn,
            const float* __restrict__ aw1,
            int n, int* sel_slot, float* arc_out,
            unsigned* key, float* acc, unsigned* ctr)
{
    __shared__ float4 sh4[512];
    __shared__ float sred[8];
    __shared__ unsigned s_ticket;
    int t = threadIdx.x;
    int g = t >> 6;
    int r = t & 63;
    int j = blockIdx.x * 4 + g;

    const float4* w4 = (const float4*)(w_a2 + (size_t)j * H);
    float4 w[8];
    #pragma unroll
    for (int i = 0; i < 8; i++) w[i] = w4[r + i * 64];

    const float4* h4 = (const float4*)h_in;
    sh4[t]       = h4[t];
    sh4[t + 256] = h4[t + 256];
    __syncthreads();

    float s = 0.0f;
    #pragma unroll
    for (int i = 0; i < 8; i++) {
        float4 h = sh4[r + i * 64];
        s += w[i].x * h.x + w[i].y * h.y + w[i].z * h.z + w[i].w * h.w;
    }
    for (int o = 16; o > 0; o >>= 1) s += __shfl_down_sync(0xffffffffu, s, o);
    if ((t & 31) == 0) sred[t >> 5] = s;
    __syncthreads();
    if (t < 4) hw2[blockIdx.x * 4 + t] = sred[2 * t] + sred[2 * t + 1];

    if (t == 0) {
        __threadfence();
        s_ticket = atomicAdd(ctr, 1u);
    }
    __syncthreads();
    if (s_ticket == gridDim.x - 1) {
        __threadfence();
        __shared__ float slog[10];
        for (int a = 0; a < n; a++) {
            float ss = 0.0f;
            for (int k = t; k < H; k += 256)
                ss += tanhf(aw1[(size_t)a * H + k] + hw2[k]) * v_attn[k];
            for (int o = 16; o > 0; o >>= 1)
                ss += __shfl_down_sync(0xffffffffu, ss, o);
            if ((t & 31) == 0) sred[t >> 5] = ss;
            __syncthreads();
            if (t == 0) {
                float tot = 0.0f;
                for (int wp = 0; wp < 8; wp++) tot += sred[wp];
                slog[a] = tot;
            }
            __syncthreads();
        }
        if (t == 0) {
            float l[10];
            for (int a = 0; a < n; a++) l[a] = 2.5f * tanhf(slog[a] / 5.0f);
            do_sample(l, n, key, acc, sel_slot, arc_out);
            *ctr = 0;
        }
    }
}

// Combined anchor projections: rows [0,H) from w1 -> out1 (aw1 slot),
// rows [H, H+G4) from w2 (STREAMED, w_ih) -> out2 (axp slot). w2 may be null.
__global__ void __launch_bounds__(256)
proj_kernel(const float* __restrict__ w1, float* __restrict__ out1,
            const float* __restrict__ w2, float* __restrict__ out2,
            const float* __restrict__ h_in)
{
    __shared__ float4 sh4[512];
    __shared__ float sred[8];
    int t = threadIdx.x;
    int g = t >> 6;
    int r = t & 63;
    int row = blockIdx.x * 4 + g;   // block never straddles H (H%4==0)

    int second = (row >= H);
    const float* W = second ? w2 : w1;
    int lrow = second ? row - H : row;
    const float4* w4 = (const float4*)(W + (size_t)lrow * H);
    float4 w[8];
    if (second) {
        #pragma unroll
        for (int i = 0; i < 8; i++) w[i] = __ldcs(&w4[r + i * 64]);
    } else {
        #pragma unroll
        for (int i = 0; i < 8; i++) w[i] = w4[r + i * 64];
    }

    const float4* h4 = (const float4*)h_in;
    sh4[t]       = h4[t];
    sh4[t + 256] = h4[t + 256];
    __syncthreads();

    float s = 0.0f;
    #pragma unroll
    for (int i = 0; i < 8; i++) {
        float4 h = sh4[r + i * 64];
        s += w[i].x * h.x + w[i].y * h.y + w[i].z * h.z + w[i].w * h.w;
    }
    for (int o = 16; o > 0; o >>= 1) s += __shfl_down_sync(0xffffffffu, s, o);
    if ((t & 31) == 0) sred[t >> 5] = s;
    __syncthreads();
    if (t < 4) {
        int rr = blockIdx.x * 4 + t;
        float v = sred[2 * t] + sred[2 * t + 1];
        if (rr < H) out1[rr] = v;
        else        out2[rr - H] = v;
    }
}

__global__ void final_kernel(const float* acc, float* out)
{
    out[64] = acc[0];
    out[65] = acc[1];
}

// ------------------------------- launcher ----------------------------------
extern "C" void kernel_launch(void* const* d_in, const int* in_sizes, int n_in,
                              void* d_out, int out_size)
{
    const float* enc    = (const float*)d_in[0];
    const float* w_ih   = (const float*)d_in[1];
    const float* b_ih   = (const float*)d_in[2];
    const float* w_hh   = (const float*)d_in[3];
    const float* b_hh   = (const float*)d_in[4];
    const float* w_soft = (const float*)d_in[5];
    const float* b_soft = (const float*)d_in[6];
    const float* b_nl   = (const float*)d_in[7];
    const float* w_a1   = (const float*)d_in[8];
    const float* w_a2   = (const float*)d_in[9];
    const float* v_at   = (const float*)d_in[10];
    float* out = (float*)d_out;

    float* scr = nullptr; unsigned* key = nullptr; float* acc = nullptr;
    int* sel = nullptr; unsigned* ctr = nullptr;
    cudaGetSymbolAddress((void**)&scr, g_scratch);
    cudaGetSymbolAddress((void**)&key, g_key);
    cudaGetSymbolAddress((void**)&acc, g_acc);
    cudaGetSymbolAddress((void**)&sel, g_sel);
    cudaGetSymbolAddress((void**)&ctr, g_ctr);

    float* hbuf[2] = { scr + OFF_H0, scr + OFF_H1 };
    float* c    = scr + OFF_C;
    float* hw2  = scr + OFF_HW2;
    float* aw1  = scr + OFF_AW1;
    float* axp  = scr + OFF_AXP;
    float* expo = scr + OFF_EXP;

    init_kernel<<<64, 256>>>(hbuf[0], c, axp, key, acc, ctr);
    encproj_kernel<<<G4, 128>>>(w_ih, enc, expo);

    #define LSTM_PLAIN(XP, SEL, OFFS) \
        lstm_kernel<<<H, 256>>>(w_hh, b_ih, b_hh, (XP), (SEL), (OFFS), \
            hbuf[hp], hbuf[hp ^ 1], c, \
            nullptr, nullptr, nullptr, 0, nullptr, nullptr, nullptr, nullptr, nullptr); \
        hp ^= 1;

    #define LSTM_OPS(XP, SEL, OFFS, UB, SLOT, ARC) \
        lstm_kernel<<<H, 256>>>(w_hh, b_ih, b_hh, (XP), (SEL), (OFFS), \
            hbuf[hp], hbuf[hp ^ 1], c, \
            w_soft, b_soft, b_nl, (UB), (SLOT), (ARC), key, acc, ctr); \
        hp ^= 1;

    int hp = 0;   // current h buffer
    int tc = 0;   // temporal decision counter (0..63)
    for (int s = 0; s < 2; s++) {
        int ub = (s == 0) ? 1 : 0;
        // warmup: 2 LSTM steps on encoder row 0; aw1[w] = h @ w_attn_1.T
        for (int w = 0; w < 2; w++) {
            LSTM_PLAIN(expo, nullptr, 0);
            proj_kernel<<<H / 4, 256>>>(w_a1, aw1 + (size_t)w * H,
                                        nullptr, nullptr, hbuf[hp]);
        }
        for (int l = 0; l < 8; l++) {
            int n = l + 2;
            int base = s * 32 + l * 4;
            // idx decision 0 (input = encoder row 0)
            LSTM_PLAIN(expo, nullptr, 0);
            attn_kernel<<<H / 4, 256>>>(w_a2, hbuf[hp], hw2, v_at, aw1, n,
                                        sel + tc, out + base + 0, key, acc,
                                        ctr + 1);
            int t0 = tc++;
            // idx decision 1 (input = anchors[idx0] -> precomputed xproj slot)
            LSTM_PLAIN(axp, sel + t0, 0);
            attn_kernel<<<H / 4, 256>>>(w_a2, hbuf[hp], hw2, v_at, aw1, n,
                                        sel + tc, out + base + 2, key, acc,
                                        ctr + 1);
            int t1 = tc++;
            // op decision 0 (input = anchors[idx1]); fused op-sample
            LSTM_OPS(axp, sel + t1, 0, ub, sel + tc, out + base + 1);
            int t2 = tc++;
            // op decision 1 (input = encoder[op0 + 1]); fused op-sample
            LSTM_OPS(expo, sel + t2, 1, ub, sel + tc, out + base + 3);
            int t3 = tc++;
            // anchor step (input = encoder[op1 + 1]); combined projections
            LSTM_PLAIN(expo, sel + t3, 1);
            proj_kernel<<<(H + G4) / 4, 256>>>(w_a1, aw1 + (size_t)n * H,
                                               w_ih, axp + (size_t)n * G4,
                                               hbuf[hp]);
        }
    }
    final_kernel<<<1, 1>>>(acc, out);

    #undef LSTM_PLAIN
    #undef LSTM_OPS
}